// round 10
// baseline (speedup 1.0000x reference)
#include <cuda_runtime.h>
#include <cuda_bf16.h>
#include <cstdint>

// ---------------------------------------------------------------------------
// Problem constants
// ---------------------------------------------------------------------------
#define BH   8
#define SS   2048
#define DH   64
#define BM   128          // q rows per CTA (8 warps x 16)
#define BN   64           // kv per tile
#define NKV  (SS / BN)    // 32

// smem: double-buffered bf16 tiles, padded rows (144B) for conflict-free LDS
#define KROWB 144
#define VROWB 144
#define OFF_KH 0
#define OFF_KL (OFF_KH + BN * KROWB)          // 9216
#define OFF_VH (OFF_KL + BN * KROWB)          // 18432
#define OFF_VL (OFF_VH + DH * VROWB)          // 27648
#define BUFB   (OFF_VL + DH * VROWB)          // 36864 per buffer
#define SMEM_ALLOC (2 * BUFB)                 // 73728

// hi/lo split of a float pair into two packed bf16x2 regs
__device__ __forceinline__ void split_pack(float a, float b, uint32_t& hi, uint32_t& lo) {
    __nv_bfloat16 ha = __float2bfloat16_rn(a);
    __nv_bfloat16 hb = __float2bfloat16_rn(b);
    float ra = a - __bfloat162float(ha);
    float rb = b - __bfloat162float(hb);
    __nv_bfloat162 th = __halves2bfloat162(ha, hb);
    __nv_bfloat162 tl = __halves2bfloat162(__float2bfloat16_rn(ra), __float2bfloat16_rn(rb));
    hi = *reinterpret_cast<uint32_t*>(&th);
    lo = *reinterpret_cast<uint32_t*>(&tl);
}

__device__ __forceinline__ void mma_bf16(float& c0, float& c1, float& c2, float& c3,
                                         uint32_t a0, uint32_t a1, uint32_t a2, uint32_t a3,
                                         uint32_t b0, uint32_t b1) {
    asm volatile(
        "mma.sync.aligned.m16n8k16.row.col.f32.bf16.bf16.f32 "
        "{%0,%1,%2,%3}, {%4,%5,%6,%7}, {%8,%9}, {%0,%1,%2,%3};"
        : "+f"(c0), "+f"(c1), "+f"(c2), "+f"(c3)
        : "r"(a0), "r"(a1), "r"(a2), "r"(a3), "r"(b0), "r"(b1));
}

__global__ void __launch_bounds__(256, 1)
fa_hmma_kernel(const float* __restrict__ Q,
               const float* __restrict__ K,
               const float* __restrict__ V,
               float* __restrict__ O)
{
    extern __shared__ char smem[];

    const int tid  = threadIdx.x;
    const int wid  = tid >> 5;
    const int lane = tid & 31;
    const int r    = lane >> 2;       // fragment row within group (0..7)
    const int c    = lane & 3;        // fragment col group (0..3)

    const int q0 = blockIdx.x * BM;
    const int h  = blockIdx.y;
    const int b  = blockIdx.z;

    const float* Qg = Q + (((size_t)b * BH + h) * SS + q0) * DH;
    const float* Kg = K + (((size_t)b * BH + h) * SS) * DH;
    const float* Vg = V + ((size_t)b * SS * BH + h) * DH;   // V[b][s][h][d]
    float*       Og = O + ((size_t)b * SS * BH + h) * DH;   // O[b][q][h][d]

    const float qscale = 0.044194173824159216f;  // 1/sqrt(512)

    // per-thread staging coordinates (same for every tile)
    const int kv_k = tid >> 4;            // K stage: kv row 0..63 per it-step offset +16
    const int d4_k = (tid & 15) * 4;      // K stage: d offset

    // ---- Q fragments in registers (loaded once, prescaled, hi/lo split) ----
    uint32_t qh[4][4], ql[4][4];      // [kstep][a0..a3]
    {
        const float* q_lo = Qg + (size_t)(wid * 16 + r) * DH;        // row r
        const float* q_hi = Qg + (size_t)(wid * 16 + r + 8) * DH;    // row r+8
        #pragma unroll
        for (int kb = 0; kb < 4; kb++) {
            int col0 = kb * 16 + c * 2;
            float2 v0 = *(const float2*)(q_lo + col0);
            float2 v1 = *(const float2*)(q_hi + col0);
            float2 v2 = *(const float2*)(q_lo + col0 + 8);
            float2 v3 = *(const float2*)(q_hi + col0 + 8);
            split_pack(v0.x * qscale, v0.y * qscale, qh[kb][0], ql[kb][0]);
            split_pack(v1.x * qscale, v1.y * qscale, qh[kb][1], ql[kb][1]);
            split_pack(v2.x * qscale, v2.y * qscale, qh[kb][2], ql[kb][2]);
            split_pack(v3.x * qscale, v3.y * qscale, qh[kb][3], ql[kb][3]);
        }
    }

    float oacc[8][4];
    #pragma unroll
    for (int i = 0; i < 8; i++)
        #pragma unroll
        for (int j = 0; j < 4; j++) oacc[i][j] = 0.0f;
    float l_lo = 0.0f, l_hi = 0.0f;

    // prefetch registers for next tile (K: 4 float4, V: 4 float4)
    float4 kpf[4];
    float4 vpf[4];

    // ---- prefetch + stage tile 0 ----
    {
        const float* Kt = Kg;
        #pragma unroll
        for (int it = 0; it < 4; it++)
            kpf[it] = *(const float4*)(Kt + (size_t)(kv_k + it * 16) * DH + d4_k);
        const float* Vt = Vg;
        #pragma unroll
        for (int it = 0; it < 2; it++) {
            int kv0 = ((it * 256 + tid) >> 4) * 2;
            vpf[2*it]   = *(const float4*)(Vt + (size_t)kv0 * BH * DH + d4_k);
            vpf[2*it+1] = *(const float4*)(Vt + (size_t)(kv0 + 1) * BH * DH + d4_k);
        }
        // convert + store to buffer 0
        char* buf = smem;
        #pragma unroll
        for (int it = 0; it < 4; it++) {
            int kv = kv_k + it * 16;
            uint32_t h0, l0, h1, l1;
            split_pack(kpf[it].x, kpf[it].y, h0, l0);
            split_pack(kpf[it].z, kpf[it].w, h1, l1);
            *(uint2*)(buf + OFF_KH + kv * KROWB + d4_k * 2) = make_uint2(h0, h1);
            *(uint2*)(buf + OFF_KL + kv * KROWB + d4_k * 2) = make_uint2(l0, l1);
        }
        #pragma unroll
        for (int it = 0; it < 2; it++) {
            int kv0 = ((it * 256 + tid) >> 4) * 2;
            float av[4] = {vpf[2*it].x, vpf[2*it].y, vpf[2*it].z, vpf[2*it].w};
            float bv[4] = {vpf[2*it+1].x, vpf[2*it+1].y, vpf[2*it+1].z, vpf[2*it+1].w};
            #pragma unroll
            for (int j = 0; j < 4; j++) {
                uint32_t hh, ll;
                split_pack(av[j], bv[j], hh, ll);
                char* base = buf + (d4_k + j) * VROWB + kv0 * 2;
                *(uint32_t*)(base + OFF_VH) = hh;
                *(uint32_t*)(base + OFF_VL) = ll;
            }
        }
    }
    __syncthreads();

    for (int kt = 0; kt < NKV; kt++) {
        char* cur = smem + (kt & 1) * BUFB;
        char* nxt = smem + ((kt + 1) & 1) * BUFB;

        // ---- issue next tile's global loads (latency hides behind MMA phase) ----
        if (kt + 1 < NKV) {
            const float* Kt = Kg + (size_t)(kt + 1) * BN * DH;
            #pragma unroll
            for (int it = 0; it < 4; it++)
                kpf[it] = *(const float4*)(Kt + (size_t)(kv_k + it * 16) * DH + d4_k);
            const float* Vt = Vg + (size_t)(kt + 1) * BN * BH * DH;
            #pragma unroll
            for (int it = 0; it < 2; it++) {
                int kv0 = ((it * 256 + tid) >> 4) * 2;
                vpf[2*it]   = *(const float4*)(Vt + (size_t)kv0 * BH * DH + d4_k);
                vpf[2*it+1] = *(const float4*)(Vt + (size_t)(kv0 + 1) * BH * DH + d4_k);
            }
        }

        // ---- S = Q K^T : 8 n-blocks, 4 k-steps, 3 split products ----
        float sacc[8][4];
        #pragma unroll
        for (int nb = 0; nb < 8; nb++)
            #pragma unroll
            for (int j = 0; j < 4; j++) sacc[nb][j] = 0.0f;

        #pragma unroll
        for (int nb = 0; nb < 8; nb++) {
            const char* krow = cur + (nb * 8 + r) * KROWB;
            #pragma unroll
            for (int kb = 0; kb < 4; kb++) {
                int dbyte = (kb * 16 + c * 2) * 2;
                uint32_t bh0 = *(const uint32_t*)(krow + OFF_KH + dbyte);
                uint32_t bh1 = *(const uint32_t*)(krow + OFF_KH + dbyte + 16);
                uint32_t bl0 = *(const uint32_t*)(krow + OFF_KL + dbyte);
                uint32_t bl1 = *(const uint32_t*)(krow + OFF_KL + dbyte + 16);
                mma_bf16(sacc[nb][0], sacc[nb][1], sacc[nb][2], sacc[nb][3],
                         qh[kb][0], qh[kb][1], qh[kb][2], qh[kb][3], bh0, bh1);
                mma_bf16(sacc[nb][0], sacc[nb][1], sacc[nb][2], sacc[nb][3],
                         qh[kb][0], qh[kb][1], qh[kb][2], qh[kb][3], bl0, bl1);
                mma_bf16(sacc[nb][0], sacc[nb][1], sacc[nb][2], sacc[nb][3],
                         ql[kb][0], ql[kb][1], ql[kb][2], ql[kb][3], bh0, bh1);
            }
        }

        // ---- exp + PV (P stays in registers) ----
        #pragma unroll
        for (int kb2 = 0; kb2 < 4; kb2++) {
            const int nba = 2 * kb2, nbb = 2 * kb2 + 1;
            float e00 = __expf(sacc[nba][0]);
            float e01 = __expf(sacc[nba][1]);
            float e02 = __expf(sacc[nba][2]);
            float e03 = __expf(sacc[nba][3]);
            float e10 = __expf(sacc[nbb][0]);
            float e11 = __expf(sacc[nbb][1]);
            float e12 = __expf(sacc[nbb][2]);
            float e13 = __expf(sacc[nbb][3]);
            l_lo += (e00 + e01) + (e10 + e11);
            l_hi += (e02 + e03) + (e12 + e13);

            uint32_t ah0, al0, ah1, al1, ah2, al2, ah3, al3;
            split_pack(e00, e01, ah0, al0);
            split_pack(e02, e03, ah1, al1);
            split_pack(e10, e11, ah2, al2);
            split_pack(e12, e13, ah3, al3);

            const char* vbase = cur + (kb2 * 16 + c * 2) * 2;
            #pragma unroll
            for (int nb = 0; nb < 8; nb++) {
                const char* vrow = vbase + (nb * 8 + r) * VROWB;
                uint32_t bh0 = *(const uint32_t*)(vrow + OFF_VH);
                uint32_t bh1 = *(const uint32_t*)(vrow + OFF_VH + 16);
                uint32_t bl0 = *(const uint32_t*)(vrow + OFF_VL);
                uint32_t bl1 = *(const uint32_t*)(vrow + OFF_VL + 16);
                mma_bf16(oacc[nb][0], oacc[nb][1], oacc[nb][2], oacc[nb][3],
                         ah0, ah1, ah2, ah3, bh0, bh1);
                mma_bf16(oacc[nb][0], oacc[nb][1], oacc[nb][2], oacc[nb][3],
                         ah0, ah1, ah2, ah3, bl0, bl1);
                mma_bf16(oacc[nb][0], oacc[nb][1], oacc[nb][2], oacc[nb][3],
                         al0, al1, al2, al3, bh0, bh1);
            }
        }

        // ---- convert prefetched regs -> other buffer (overlaps others' MMAs) ----
        if (kt + 1 < NKV) {
            #pragma unroll
            for (int it = 0; it < 4; it++) {
                int kv = kv_k + it * 16;
                uint32_t h0, l0, h1, l1;
                split_pack(kpf[it].x, kpf[it].y, h0, l0);
                split_pack(kpf[it].z, kpf[it].w, h1, l1);
                *(uint2*)(nxt + OFF_KH + kv * KROWB + d4_k * 2) = make_uint2(h0, h1);
                *(uint2*)(nxt + OFF_KL + kv * KROWB + d4_k * 2) = make_uint2(l0, l1);
            }
            #pragma unroll
            for (int it = 0; it < 2; it++) {
                int kv0 = ((it * 256 + tid) >> 4) * 2;
                float av[4] = {vpf[2*it].x, vpf[2*it].y, vpf[2*it].z, vpf[2*it].w};
                float bv[4] = {vpf[2*it+1].x, vpf[2*it+1].y, vpf[2*it+1].z, vpf[2*it+1].w};
                #pragma unroll
                for (int j = 0; j < 4; j++) {
                    uint32_t hh, ll;
                    split_pack(av[j], bv[j], hh, ll);
                    char* base = nxt + (d4_k + j) * VROWB + kv0 * 2;
                    *(uint32_t*)(base + OFF_VH) = hh;
                    *(uint32_t*)(base + OFF_VL) = ll;
                }
            }
        }
        __syncthreads();
    }

    // ---- reduce softmax denominators across the 4 lanes sharing a row ----
    l_lo += __shfl_xor_sync(0xffffffffu, l_lo, 1);
    l_lo += __shfl_xor_sync(0xffffffffu, l_lo, 2);
    l_hi += __shfl_xor_sync(0xffffffffu, l_hi, 1);
    l_hi += __shfl_xor_sync(0xffffffffu, l_hi, 2);
    const float inv_lo = 1.0f / l_lo;
    const float inv_hi = 1.0f / l_hi;

    // ---- store O[b][q][h][d] ----
    {
        float* o_lo = Og + (size_t)(q0 + wid * 16 + r) * BH * DH;
        float* o_hi = Og + (size_t)(q0 + wid * 16 + r + 8) * BH * DH;
        #pragma unroll
        for (int nb = 0; nb < 8; nb++) {
            int d0 = nb * 8 + c * 2;
            float2 vlo = make_float2(oacc[nb][0] * inv_lo, oacc[nb][1] * inv_lo);
            float2 vhi = make_float2(oacc[nb][2] * inv_hi, oacc[nb][3] * inv_hi);
            *(float2*)(o_lo + d0) = vlo;
            *(float2*)(o_hi + d0) = vhi;
        }
    }
}

extern "C" void kernel_launch(void* const* d_in, const int* in_sizes, int n_in,
                              void* d_out, int out_size)
{
    const float* Q = (const float*)d_in[0];
    const float* K = (const float*)d_in[1];
    const float* V = (const float*)d_in[2];
    float*       O = (float*)d_out;

    cudaFuncSetAttribute(fa_hmma_kernel,
                         cudaFuncAttributeMaxDynamicSharedMemorySize, SMEM_ALLOC);

    dim3 grid(SS / BM, BH, 4);   // (16, 8, 4) = 512 CTAs
    fa_hmma_kernel<<<grid, 256, SMEM_ALLOC>>>(Q, K, V, O);
}

// round 11
// speedup vs baseline: 2.2477x; 2.2477x over previous
#include <cuda_runtime.h>
#include <cuda_fp16.h>
#include <cstdint>

// ---------------------------------------------------------------------------
// Problem constants
// ---------------------------------------------------------------------------
#define BH   8
#define SS   2048
#define DH   64
#define BM   128          // q rows per CTA (8 warps x 16)
#define BN   64           // kv per tile
#define NKV  (SS / BN)    // 32

// smem: double-buffered fp16 tiles, padded rows (144B) for conflict-free LDS
#define KROWB 144
#define VROWB 144
#define OFF_K  0
#define OFF_V  (BN * KROWB)                   // 9216
#define BUFB   (OFF_V + DH * VROWB)           // 18432 per buffer
#define SMEM_ALLOC (2 * BUFB)                 // 36864

__device__ __forceinline__ uint32_t pack_h2(float a, float b) {
    __half2 t = __floats2half2_rn(a, b);
    return *reinterpret_cast<uint32_t*>(&t);
}

__device__ __forceinline__ void mma_f16(float& c0, float& c1, float& c2, float& c3,
                                        uint32_t a0, uint32_t a1, uint32_t a2, uint32_t a3,
                                        uint32_t b0, uint32_t b1) {
    asm volatile(
        "mma.sync.aligned.m16n8k16.row.col.f32.f16.f16.f32 "
        "{%0,%1,%2,%3}, {%4,%5,%6,%7}, {%8,%9}, {%0,%1,%2,%3};"
        : "+f"(c0), "+f"(c1), "+f"(c2), "+f"(c3)
        : "r"(a0), "r"(a1), "r"(a2), "r"(a3), "r"(b0), "r"(b1));
}

__global__ void __launch_bounds__(256, 1)
fa_hmma_kernel(const float* __restrict__ Q,
               const float* __restrict__ K,
               const float* __restrict__ V,
               float* __restrict__ O)
{
    extern __shared__ char smem[];

    const int tid  = threadIdx.x;
    const int wid  = tid >> 5;
    const int lane = tid & 31;
    const int r    = lane >> 2;       // fragment row within group (0..7)
    const int c    = lane & 3;        // fragment col group (0..3)

    const int q0 = blockIdx.x * BM;
    const int h  = blockIdx.y;
    const int b  = blockIdx.z;

    const float* Qg = Q + (((size_t)b * BH + h) * SS + q0) * DH;
    const float* Kg = K + (((size_t)b * BH + h) * SS) * DH;
    const float* Vg = V + ((size_t)b * SS * BH + h) * DH;   // V[b][s][h][d]
    float*       Og = O + ((size_t)b * SS * BH + h) * DH;   // O[b][q][h][d]

    const float qscale = 0.044194173824159216f;  // 1/sqrt(512)

    // per-thread staging coordinates (same for every tile)
    const int kv_k = tid >> 4;            // K stage: kv row, +16 per it-step
    const int d4_k = (tid & 15) * 4;      // d offset

    // ---- Q fragments in registers (loaded once, prescaled, fp16) ----
    uint32_t qf[4][4];                    // [kstep][a0..a3]
    {
        const float* q_lo = Qg + (size_t)(wid * 16 + r) * DH;        // row r
        const float* q_hi = Qg + (size_t)(wid * 16 + r + 8) * DH;    // row r+8
        #pragma unroll
        for (int kb = 0; kb < 4; kb++) {
            int col0 = kb * 16 + c * 2;
            float2 v0 = *(const float2*)(q_lo + col0);
            float2 v1 = *(const float2*)(q_hi + col0);
            float2 v2 = *(const float2*)(q_lo + col0 + 8);
            float2 v3 = *(const float2*)(q_hi + col0 + 8);
            qf[kb][0] = pack_h2(v0.x * qscale, v0.y * qscale);
            qf[kb][1] = pack_h2(v1.x * qscale, v1.y * qscale);
            qf[kb][2] = pack_h2(v2.x * qscale, v2.y * qscale);
            qf[kb][3] = pack_h2(v3.x * qscale, v3.y * qscale);
        }
    }

    float oacc[8][4];
    #pragma unroll
    for (int i = 0; i < 8; i++)
        #pragma unroll
        for (int j = 0; j < 4; j++) oacc[i][j] = 0.0f;
    float l_lo = 0.0f, l_hi = 0.0f;

    // prefetch registers for next tile (K: 4 float4, V: 4 float4)
    float4 kpf[4];
    float4 vpf[4];

    // ---- prefetch + stage tile 0 ----
    {
        const float* Kt = Kg;
        #pragma unroll
        for (int it = 0; it < 4; it++)
            kpf[it] = *(const float4*)(Kt + (size_t)(kv_k + it * 16) * DH + d4_k);
        const float* Vt = Vg;
        #pragma unroll
        for (int it = 0; it < 2; it++) {
            int kv0 = ((it * 256 + tid) >> 4) * 2;
            vpf[2*it]   = *(const float4*)(Vt + (size_t)kv0 * BH * DH + d4_k);
            vpf[2*it+1] = *(const float4*)(Vt + (size_t)(kv0 + 1) * BH * DH + d4_k);
        }
        char* buf = smem;
        #pragma unroll
        for (int it = 0; it < 4; it++) {
            int kv = kv_k + it * 16;
            uint2 hv = make_uint2(pack_h2(kpf[it].x, kpf[it].y),
                                  pack_h2(kpf[it].z, kpf[it].w));
            *(uint2*)(buf + OFF_K + kv * KROWB + d4_k * 2) = hv;
        }
        #pragma unroll
        for (int it = 0; it < 2; it++) {
            int kv0 = ((it * 256 + tid) >> 4) * 2;
            float av[4] = {vpf[2*it].x, vpf[2*it].y, vpf[2*it].z, vpf[2*it].w};
            float bv[4] = {vpf[2*it+1].x, vpf[2*it+1].y, vpf[2*it+1].z, vpf[2*it+1].w};
            #pragma unroll
            for (int j = 0; j < 4; j++)
                *(uint32_t*)(buf + OFF_V + (d4_k + j) * VROWB + kv0 * 2) =
                    pack_h2(av[j], bv[j]);
        }
    }
    __syncthreads();

    for (int kt = 0; kt < NKV; kt++) {
        char* cur = smem + (kt & 1) * BUFB;
        char* nxt = smem + ((kt + 1) & 1) * BUFB;

        // ---- issue next tile's global loads (hide behind MMA phase) ----
        if (kt + 1 < NKV) {
            const float* Kt = Kg + (size_t)(kt + 1) * BN * DH;
            #pragma unroll
            for (int it = 0; it < 4; it++)
                kpf[it] = *(const float4*)(Kt + (size_t)(kv_k + it * 16) * DH + d4_k);
            const float* Vt = Vg + (size_t)(kt + 1) * BN * BH * DH;
            #pragma unroll
            for (int it = 0; it < 2; it++) {
                int kv0 = ((it * 256 + tid) >> 4) * 2;
                vpf[2*it]   = *(const float4*)(Vt + (size_t)kv0 * BH * DH + d4_k);
                vpf[2*it+1] = *(const float4*)(Vt + (size_t)(kv0 + 1) * BH * DH + d4_k);
            }
        }

        // ---- S = Q K^T : 8 n-blocks x 4 k-steps, single fp16 product ----
        float sacc[8][4];
        #pragma unroll
        for (int nb = 0; nb < 8; nb++)
            #pragma unroll
            for (int j = 0; j < 4; j++) sacc[nb][j] = 0.0f;

        #pragma unroll
        for (int nb = 0; nb < 8; nb++) {
            const char* krow = cur + OFF_K + (nb * 8 + r) * KROWB;
            #pragma unroll
            for (int kb = 0; kb < 4; kb++) {
                int dbyte = (kb * 16 + c * 2) * 2;
                uint32_t b0 = *(const uint32_t*)(krow + dbyte);
                uint32_t b1 = *(const uint32_t*)(krow + dbyte + 16);
                mma_f16(sacc[nb][0], sacc[nb][1], sacc[nb][2], sacc[nb][3],
                        qf[kb][0], qf[kb][1], qf[kb][2], qf[kb][3], b0, b1);
            }
        }

        // ---- exp + PV (P stays in registers: D-frag layout == A-frag layout) ----
        #pragma unroll
        for (int kb2 = 0; kb2 < 4; kb2++) {
            const int nba = 2 * kb2, nbb = 2 * kb2 + 1;
            float e00 = __expf(sacc[nba][0]);
            float e01 = __expf(sacc[nba][1]);
            float e02 = __expf(sacc[nba][2]);
            float e03 = __expf(sacc[nba][3]);
            float e10 = __expf(sacc[nbb][0]);
            float e11 = __expf(sacc[nbb][1]);
            float e12 = __expf(sacc[nbb][2]);
            float e13 = __expf(sacc[nbb][3]);
            l_lo += (e00 + e01) + (e10 + e11);
            l_hi += (e02 + e03) + (e12 + e13);

            uint32_t a0 = pack_h2(e00, e01);   // row r,   k 0..1 of step
            uint32_t a1 = pack_h2(e02, e03);   // row r+8
            uint32_t a2 = pack_h2(e10, e11);   // row r,   k 8..9
            uint32_t a3 = pack_h2(e12, e13);   // row r+8

            const char* vbase = cur + OFF_V + (kb2 * 16 + c * 2) * 2;
            #pragma unroll
            for (int nb = 0; nb < 8; nb++) {
                const char* vrow = vbase + (nb * 8 + r) * VROWB;
                uint32_t b0 = *(const uint32_t*)(vrow);
                uint32_t b1 = *(const uint32_t*)(vrow + 16);
                mma_f16(oacc[nb][0], oacc[nb][1], oacc[nb][2], oacc[nb][3],
                        a0, a1, a2, a3, b0, b1);
            }
        }

        // ---- convert prefetched regs -> other buffer (overlaps MMAs) ----
        if (kt + 1 < NKV) {
            #pragma unroll
            for (int it = 0; it < 4; it++) {
                int kv = kv_k + it * 16;
                uint2 hv = make_uint2(pack_h2(kpf[it].x, kpf[it].y),
                                      pack_h2(kpf[it].z, kpf[it].w));
                *(uint2*)(nxt + OFF_K + kv * KROWB + d4_k * 2) = hv;
            }
            #pragma unroll
            for (int it = 0; it < 2; it++) {
                int kv0 = ((it * 256 + tid) >> 4) * 2;
                float av[4] = {vpf[2*it].x, vpf[2*it].y, vpf[2*it].z, vpf[2*it].w};
                float bv[4] = {vpf[2*it+1].x, vpf[2*it+1].y, vpf[2*it+1].z, vpf[2*it+1].w};
                #pragma unroll
                for (int j = 0; j < 4; j++)
                    *(uint32_t*)(nxt + OFF_V + (d4_k + j) * VROWB + kv0 * 2) =
                        pack_h2(av[j], bv[j]);
            }
        }
        __syncthreads();
    }

    // ---- reduce softmax denominators across the 4 lanes sharing a row ----
    l_lo += __shfl_xor_sync(0xffffffffu, l_lo, 1);
    l_lo += __shfl_xor_sync(0xffffffffu, l_lo, 2);
    l_hi += __shfl_xor_sync(0xffffffffu, l_hi, 1);
    l_hi += __shfl_xor_sync(0xffffffffu, l_hi, 2);
    const float inv_lo = 1.0f / l_lo;
    const float inv_hi = 1.0f / l_hi;

    // ---- store O[b][q][h][d] ----
    {
        float* o_lo = Og + (size_t)(q0 + wid * 16 + r) * BH * DH;
        float* o_hi = Og + (size_t)(q0 + wid * 16 + r + 8) * BH * DH;
        #pragma unroll
        for (int nb = 0; nb < 8; nb++) {
            int d0 = nb * 8 + c * 2;
            float2 vlo = make_float2(oacc[nb][0] * inv_lo, oacc[nb][1] * inv_lo);
            float2 vhi = make_float2(oacc[nb][2] * inv_hi, oacc[nb][3] * inv_hi);
            *(float2*)(o_lo + d0) = vlo;
            *(float2*)(o_hi + d0) = vhi;
        }
    }
}

extern "C" void kernel_launch(void* const* d_in, const int* in_sizes, int n_in,
                              void* d_out, int out_size)
{
    const float* Q = (const float*)d_in[0];
    const float* K = (const float*)d_in[1];
    const float* V = (const float*)d_in[2];
    float*       O = (float*)d_out;

    cudaFuncSetAttribute(fa_hmma_kernel,
                         cudaFuncAttributeMaxDynamicSharedMemorySize, SMEM_ALLOC);

    dim3 grid(SS / BM, BH, 4);   // (16, 8, 4) = 512 CTAs
    fa_hmma_kernel<<<grid, 256, SMEM_ALLOC>>>(Q, K, V, O);
}